// round 3
// baseline (speedup 1.0000x reference)
#include <cuda_runtime.h>
#include <cuda_bf16.h>
#include <cstdint>

#define IN_F 4096
#define OUT_F 4096
#define M_TOTAL 16384

#define TILE_M 128
#define TILE_N 128
#define TILE_K 64                      // K elems per chunk (128B bf16 row, 64B fp8 half-rows)
#define NC (IN_F / TILE_K)             // 64
#define THREADS 256
#define STAGES 3

// stage layout (bytes): Ah(bf16) | Aq(fp8 [Ah|256Al]) | Wh(bf16) | Wq(fp8 [4096Wl|16Wh])
#define AH_OFF 0
#define AQ_OFF 16384
#define WH_OFF 32768
#define WQ_OFF 49152
#define STAGE_BYTES 65536
#define SMEM_TOTAL (STAGES * STAGE_BYTES)   // 196608

#define CROSS_SCALE (1.0f / 4096.0f)

// ---------------- device scratch ----------------
__device__ __nv_bfloat16 g_Whi[(size_t)OUT_F * IN_F];
__device__ unsigned char g_Wqh[(size_t)OUT_F * IN_F];   // e4m3(16*Wh)
__device__ unsigned char g_Wql[(size_t)OUT_F * IN_F];   // e4m3(4096*Wl)
__device__ __nv_bfloat16 g_Ahi[(size_t)M_TOTAL * IN_F];
__device__ unsigned char g_Aqh[(size_t)M_TOTAL * IN_F]; // e4m3(Ah)
__device__ unsigned char g_Aql[(size_t)M_TOTAL * IN_F]; // e4m3(256*Al)

// ---------------- helpers ----------------
static __device__ __forceinline__ uint32_t smem_u32_of(const void* p) {
    uint32_t r;
    asm("{ .reg .u64 t; cvta.to.shared.u64 t, %1; cvt.u32.u64 %0, t; }" : "=r"(r) : "l"(p));
    return r;
}
static __device__ __forceinline__ void cp16(uint32_t dst, const void* src) {
    asm volatile("cp.async.cg.shared.global [%0], [%1], 16;" :: "r"(dst), "l"(src));
}
static __device__ __forceinline__ void ldsm4(uint32_t (&r)[4], uint32_t a) {
    asm volatile("ldmatrix.sync.aligned.m8n8.x4.shared.b16 {%0,%1,%2,%3}, [%4];"
                 : "=r"(r[0]), "=r"(r[1]), "=r"(r[2]), "=r"(r[3]) : "r"(a));
}
static __device__ __forceinline__ void mma_bf16(float (&d)[4], const uint32_t (&a)[4],
                                                uint32_t b0, uint32_t b1) {
    asm volatile(
        "mma.sync.aligned.m16n8k16.row.col.f32.bf16.bf16.f32 "
        "{%0,%1,%2,%3}, {%4,%5,%6,%7}, {%8,%9}, {%0,%1,%2,%3};"
        : "+f"(d[0]), "+f"(d[1]), "+f"(d[2]), "+f"(d[3])
        : "r"(a[0]), "r"(a[1]), "r"(a[2]), "r"(a[3]), "r"(b0), "r"(b1));
}
static __device__ __forceinline__ void mma_fp8(float (&d)[4], const uint32_t (&a)[4],
                                               uint32_t b0, uint32_t b1) {
    asm volatile(
        "mma.sync.aligned.m16n8k32.row.col.f32.e4m3.e4m3.f32 "
        "{%0,%1,%2,%3}, {%4,%5,%6,%7}, {%8,%9}, {%0,%1,%2,%3};"
        : "+f"(d[0]), "+f"(d[1]), "+f"(d[2]), "+f"(d[3])
        : "r"(a[0]), "r"(a[1]), "r"(a[2]), "r"(a[3]), "r"(b0), "r"(b1));
}

// pack 4 floats -> 4 e4m3 bytes (byte0 = f0)
static __device__ __forceinline__ uint32_t pack_e4m3_4(float f0, float f1, float f2, float f3) {
    uint16_t p01, p23;
    asm("cvt.rn.satfinite.e4m3x2.f32 %0, %1, %2;" : "=h"(p01) : "f"(f1), "f"(f0));
    asm("cvt.rn.satfinite.e4m3x2.f32 %0, %1, %2;" : "=h"(p23) : "f"(f3), "f"(f2));
    return (uint32_t)p01 | ((uint32_t)p23 << 16);
}
static __device__ __forceinline__ unsigned char cvt_e4m3_1(float f) {
    uint16_t p;
    asm("cvt.rn.satfinite.e4m3x2.f32 %0, %1, %2;" : "=h"(p) : "f"(f), "f"(f));
    return (unsigned char)(p & 0xFF);
}

// ---------------- prep kernel 1: split W and A (fused) ----------------
__global__ void prep_split(const float* __restrict__ W, const float* __restrict__ A) {
    const size_t NW4 = (size_t)OUT_F * IN_F / 4;
    const size_t NA4 = (size_t)M_TOTAL * IN_F / 4;
    for (size_t j = (size_t)blockIdx.x * blockDim.x + threadIdx.x; j < NW4 + NA4;
         j += (size_t)gridDim.x * blockDim.x) {
        if (j < NW4) {
            float4 v = reinterpret_cast<const float4*>(W)[j];
            __nv_bfloat16 h0 = __float2bfloat16(v.x), h1 = __float2bfloat16(v.y),
                          h2 = __float2bfloat16(v.z), h3 = __float2bfloat16(v.w);
            float hf0 = __bfloat162float(h0), hf1 = __bfloat162float(h1),
                  hf2 = __bfloat162float(h2), hf3 = __bfloat162float(h3);
            reinterpret_cast<ushort4*>(g_Whi)[j] =
                make_ushort4(__bfloat16_as_ushort(h0), __bfloat16_as_ushort(h1),
                             __bfloat16_as_ushort(h2), __bfloat16_as_ushort(h3));
            reinterpret_cast<uint32_t*>(g_Wqh)[j] =
                pack_e4m3_4(16.f * hf0, 16.f * hf1, 16.f * hf2, 16.f * hf3);
            reinterpret_cast<uint32_t*>(g_Wql)[j] =
                pack_e4m3_4(4096.f * (v.x - hf0), 4096.f * (v.y - hf1),
                            4096.f * (v.z - hf2), 4096.f * (v.w - hf3));
        } else {
            size_t i = j - NW4;
            float4 v = reinterpret_cast<const float4*>(A)[i];
            __nv_bfloat16 h0 = __float2bfloat16(v.x), h1 = __float2bfloat16(v.y),
                          h2 = __float2bfloat16(v.z), h3 = __float2bfloat16(v.w);
            float hf0 = __bfloat162float(h0), hf1 = __bfloat162float(h1),
                  hf2 = __bfloat162float(h2), hf3 = __bfloat162float(h3);
            reinterpret_cast<ushort4*>(g_Ahi)[i] =
                make_ushort4(__bfloat16_as_ushort(h0), __bfloat16_as_ushort(h1),
                             __bfloat16_as_ushort(h2), __bfloat16_as_ushort(h3));
            reinterpret_cast<uint32_t*>(g_Aqh)[i] = pack_e4m3_4(hf0, hf1, hf2, hf3);
            reinterpret_cast<uint32_t*>(g_Aql)[i] =
                pack_e4m3_4(256.f * (v.x - hf0), 256.f * (v.y - hf1),
                            256.f * (v.z - hf2), 256.f * (v.w - hf3));
        }
    }
}

// ---------------- prep kernel 2: sorted scatter, unique-leader rewrite ----------------
__global__ void scatter_fix(const float* __restrict__ sw, const int* __restrict__ idx,
                            const float* __restrict__ W, int nnz) {
    int i = blockIdx.x * blockDim.x + threadIdx.x;
    if (i >= nnz) return;
    int v = idx[i];
    if (i > 0 && idx[i - 1] == v) return;  // not segment leader
    float s = sw[i];
    for (int j = i + 1; j < nnz && idx[j] == v; ++j) s += sw[j];
    float w = W[v] + s;
    __nv_bfloat16 h = __float2bfloat16(w);
    float hf = __bfloat162float(h);
    float l = w - hf;
    g_Whi[v] = h;
    g_Wqh[v] = cvt_e4m3_1(16.f * hf);
    g_Wql[v] = cvt_e4m3_1(4096.f * l);
}

// ---------------- GEMM ----------------
// out[m,n] = (Ah.Wh)_bf16 + (Ah.4096Wl + 256Al.16Wh)_fp8 / 4096 + bias[n]
__global__ void __launch_bounds__(THREADS, 1)
gemm_kernel(const float* __restrict__ bias, float* __restrict__ out) {
    extern __shared__ __align__(128) char smem[];
    const uint32_t sbase = smem_u32_of(smem);

    const int tid  = threadIdx.x;
    const int lane = tid & 31;
    const int wid  = tid >> 5;        // 8 warps
    const int wm   = wid & 1;         // 2 rows of warps (64 m each)
    const int wn   = wid >> 1;        // 4 cols of warps (32 n each)
    const int mBase = blockIdx.y * TILE_M;
    const int nBase = blockIdx.x * TILE_N;

    float accM[4][4][4], accC[4][4][4];
#pragma unroll
    for (int f = 0; f < 4; ++f)
#pragma unroll
        for (int g = 0; g < 4; ++g)
#pragma unroll
            for (int r = 0; r < 4; ++r) { accM[f][g][r] = 0.f; accC[f][g][r] = 0.f; }

    // ---- async copy one k-chunk into stage s ----
    auto issue_stage = [&](int s, int chunk) {
        const int kB = chunk * TILE_K;
        const uint32_t st = sbase + (uint32_t)s * STAGE_BYTES;
#pragma unroll
        for (int j = 0; j < 4; ++j) {
            int i = tid + j * THREADS;        // 0..1023
            int row = i >> 3, b = i & 7;
            uint32_t so = (uint32_t)(row * 128) + (uint32_t)(((b ^ (row & 7)) << 4));
            const size_t aofs = (size_t)(mBase + row) * IN_F + kB;
            const size_t wofs = (size_t)(nBase + row) * IN_F + kB;
            cp16(st + AH_OFF + so, g_Ahi + aofs + b * 8);
            cp16(st + WH_OFF + so, g_Whi + wofs + b * 8);
            const void* aq = (b < 4) ? (const void*)(g_Aqh + aofs + b * 16)
                                     : (const void*)(g_Aql + aofs + (b - 4) * 16);
            const void* wq = (b < 4) ? (const void*)(g_Wql + wofs + b * 16)
                                     : (const void*)(g_Wqh + wofs + (b - 4) * 16);
            cp16(st + AQ_OFF + so, aq);
            cp16(st + WQ_OFF + so, wq);
        }
        asm volatile("cp.async.commit_group;" ::: "memory");
    };

    const int rA  = wm * 64 + (lane & 15);
    const int rB  = wn * 32 + (lane & 15);
    const int hi  = lane >> 4;
    const int r7A = rA & 7;
    const int r7B = rB & 7;

    auto compute = [&](int s) {
        const uint32_t st  = sbase + (uint32_t)s * STAGE_BYTES;
        const uint32_t sAH = st + AH_OFF + (uint32_t)(rA * 128);
        const uint32_t sAQ = st + AQ_OFF + (uint32_t)(rA * 128);
        const uint32_t sWH = st + WH_OFF + (uint32_t)(rB * 128);
        const uint32_t sWQ = st + WQ_OFF + (uint32_t)(rB * 128);
#pragma unroll
        for (int ks = 0; ks < 4; ++ks) {
            const uint32_t cA = (uint32_t)(((2 * ks + hi) ^ r7A) << 4);
            const uint32_t cB = (uint32_t)(((2 * ks + hi) ^ r7B) << 4);
            uint32_t Bh0[4], Bh1[4], Bq0[4], Bq1[4];
            ldsm4(Bh0, sWH + cB);
            ldsm4(Bh1, sWH + 16 * 128 + cB);
            ldsm4(Bq0, sWQ + cB);
            ldsm4(Bq1, sWQ + 16 * 128 + cB);
#pragma unroll
            for (int f = 0; f < 4; ++f) {
                uint32_t a[4], q[4];
                ldsm4(a, sAH + (uint32_t)(f * 16 * 128) + cA);
                mma_bf16(accM[f][0], a, Bh0[0], Bh0[2]);
                mma_bf16(accM[f][1], a, Bh0[1], Bh0[3]);
                mma_bf16(accM[f][2], a, Bh1[0], Bh1[2]);
                mma_bf16(accM[f][3], a, Bh1[1], Bh1[3]);
                ldsm4(q, sAQ + (uint32_t)(f * 16 * 128) + cA);
                mma_fp8(accC[f][0], q, Bq0[0], Bq0[2]);
                mma_fp8(accC[f][1], q, Bq0[1], Bq0[3]);
                mma_fp8(accC[f][2], q, Bq1[0], Bq1[2]);
                mma_fp8(accC[f][3], q, Bq1[1], Bq1[3]);
            }
        }
    };

    // ---- 3-stage pipelined mainloop ----
    issue_stage(0, 0);
    issue_stage(1, 1);
#pragma unroll 1
    for (int c = 0; c < NC; ++c) {
        if (c + 2 < NC) {
            issue_stage((c + 2) % STAGES, c + 2);
            asm volatile("cp.async.wait_group 2;" ::: "memory");
        } else if (c + 1 < NC) {
            asm volatile("cp.async.wait_group 1;" ::: "memory");
        } else {
            asm volatile("cp.async.wait_group 0;" ::: "memory");
        }
        __syncthreads();
        compute(c % STAGES);
        __syncthreads();
    }

    // ---- epilogue ----
    const int row0 = mBase + wm * 64 + (lane >> 2);
    const int col0 = nBase + wn * 32 + (lane & 3) * 2;
#pragma unroll
    for (int g = 0; g < 4; ++g) {
        const float b0 = __ldg(bias + col0 + g * 8);
        const float b1 = __ldg(bias + col0 + g * 8 + 1);
#pragma unroll
        for (int f = 0; f < 4; ++f) {
            const int r = row0 + f * 16;
            float2 v0, v1;
            v0.x = accM[f][g][0] + accC[f][g][0] * CROSS_SCALE + b0;
            v0.y = accM[f][g][1] + accC[f][g][1] * CROSS_SCALE + b1;
            v1.x = accM[f][g][2] + accC[f][g][2] * CROSS_SCALE + b0;
            v1.y = accM[f][g][3] + accC[f][g][3] * CROSS_SCALE + b1;
            *reinterpret_cast<float2*>(out + (size_t)r * OUT_F + col0 + g * 8) = v0;
            *reinterpret_cast<float2*>(out + (size_t)(r + 8) * OUT_F + col0 + g * 8) = v1;
        }
    }
}

// ---------------- launch (3 launches per call -> ncu -s5 lands on gemm) ----------------
extern "C" void kernel_launch(void* const* d_in, const int* in_sizes, int n_in,
                              void* d_out, int out_size) {
    const float* input    = (const float*)d_in[0];   // [8,2048,4096]
    const float* dense_w  = (const float*)d_in[1];   // [4096,4096]
    const float* dense_b  = (const float*)d_in[2];   // [4096]
    const float* sparse_w = (const float*)d_in[3];   // [NNZ]
    const int*   nz_idx   = (const int*)d_in[4];     // [NNZ] sorted
    float* out = (float*)d_out;                      // [8,2048,4096] fp32
    const int nnz = in_sizes[3];

    prep_split<<<8192, 256>>>(dense_w, input);
    scatter_fix<<<(nnz + 255) / 256, 256>>>(sparse_w, nz_idx, dense_w, nnz);

    cudaFuncSetAttribute(gemm_kernel, cudaFuncAttributeMaxDynamicSharedMemorySize, SMEM_TOTAL);
    gemm_kernel<<<dim3(OUT_F / TILE_N, M_TOTAL / TILE_M), THREADS, SMEM_TOTAL>>>(dense_b, out);
}

// round 4
// speedup vs baseline: 2.9797x; 2.9797x over previous
#include <cuda_runtime.h>
#include <cuda_fp16.h>
#include <cstdint>

#define IN_F 4096
#define OUT_F 4096
#define M_TOTAL 16384

#define TILE_M 128
#define TILE_N 256
#define TILE_K 64                       // fp16 elems per chunk = 128 B smem rows
#define NC (IN_F / TILE_K)              // 64
#define THREADS 512
#define STAGES 3

// stage layout (bytes): A (128 rows x 128B) | B (256 rows x 128B)
#define A_OFF 0
#define B_OFF (TILE_M * 128)                      // 16384
#define STAGE_BYTES ((TILE_M + TILE_N) * 128)     // 49152
#define SMEM_TOTAL (STAGES * STAGE_BYTES)         // 147456

// ---------------- device scratch ----------------
__device__ __half g_Wh[(size_t)OUT_F * IN_F];
__device__ __half g_Ah[(size_t)M_TOTAL * IN_F];

// ---------------- helpers ----------------
static __device__ __forceinline__ uint32_t smem_u32_of(const void* p) {
    uint32_t r;
    asm("{ .reg .u64 t; cvta.to.shared.u64 t, %1; cvt.u32.u64 %0, t; }" : "=r"(r) : "l"(p));
    return r;
}
static __device__ __forceinline__ void cp16(uint32_t dst, const void* src) {
    asm volatile("cp.async.cg.shared.global [%0], [%1], 16;" :: "r"(dst), "l"(src));
}
static __device__ __forceinline__ void ldsm4(uint32_t (&r)[4], uint32_t a) {
    asm volatile("ldmatrix.sync.aligned.m8n8.x4.shared.b16 {%0,%1,%2,%3}, [%4];"
                 : "=r"(r[0]), "=r"(r[1]), "=r"(r[2]), "=r"(r[3]) : "r"(a));
}
static __device__ __forceinline__ void mma_f16(float (&d)[4], const uint32_t (&a)[4],
                                               uint32_t b0, uint32_t b1) {
    asm volatile(
        "mma.sync.aligned.m16n8k16.row.col.f32.f16.f16.f32 "
        "{%0,%1,%2,%3}, {%4,%5,%6,%7}, {%8,%9}, {%0,%1,%2,%3};"
        : "+f"(d[0]), "+f"(d[1]), "+f"(d[2]), "+f"(d[3])
        : "r"(a[0]), "r"(a[1]), "r"(a[2]), "r"(a[3]), "r"(b0), "r"(b1));
}

// ---------------- prep kernel 1: fp32 -> fp16 convert (W then A) ----------------
__global__ void prep_convert(const float* __restrict__ W, const float* __restrict__ A) {
    const size_t NW4 = (size_t)OUT_F * IN_F / 4;
    const size_t NA4 = (size_t)M_TOTAL * IN_F / 4;
    for (size_t j = (size_t)blockIdx.x * blockDim.x + threadIdx.x; j < NW4 + NA4;
         j += (size_t)gridDim.x * blockDim.x) {
        if (j < NW4) {
            float4 v = reinterpret_cast<const float4*>(W)[j];
            __half2 p0 = __floats2half2_rn(v.x, v.y);
            __half2 p1 = __floats2half2_rn(v.z, v.w);
            reinterpret_cast<uint2*>(g_Wh)[j] =
                make_uint2(*reinterpret_cast<uint32_t*>(&p0), *reinterpret_cast<uint32_t*>(&p1));
        } else {
            size_t i = j - NW4;
            float4 v = reinterpret_cast<const float4*>(A)[i];
            __half2 p0 = __floats2half2_rn(v.x, v.y);
            __half2 p1 = __floats2half2_rn(v.z, v.w);
            reinterpret_cast<uint2*>(g_Ah)[i] =
                make_uint2(*reinterpret_cast<uint32_t*>(&p0), *reinterpret_cast<uint32_t*>(&p1));
        }
    }
}

// ---------------- prep kernel 2: sorted scatter, unique-leader rewrite ----------------
__global__ void scatter_fix(const float* __restrict__ sw, const int* __restrict__ idx,
                            const float* __restrict__ W, int nnz) {
    int i = blockIdx.x * blockDim.x + threadIdx.x;
    if (i >= nnz) return;
    int v = idx[i];
    if (i > 0 && idx[i - 1] == v) return;  // not segment leader
    float s = sw[i];
    for (int j = i + 1; j < nnz && idx[j] == v; ++j) s += sw[j];
    g_Wh[v] = __float2half_rn(W[v] + s);
}

// ---------------- GEMM: out[m,n] = sum_k A[m,k]*W[n,k] + bias[n] (single fp16 pass) ----
__global__ void __launch_bounds__(THREADS, 1)
gemm_kernel(const float* __restrict__ bias, float* __restrict__ out) {
    extern __shared__ __align__(128) char smem[];
    const uint32_t sbase = smem_u32_of(smem);

    const int tid  = threadIdx.x;
    const int lane = tid & 31;
    const int wid  = tid >> 5;        // 16 warps
    const int wm   = wid & 1;         // 2 warp rows (64 m each)
    const int wn   = wid >> 1;        // 8 warp cols (32 n each)
    const int mBase = blockIdx.y * TILE_M;
    const int nBase = blockIdx.x * TILE_N;

    float acc[4][4][4];
#pragma unroll
    for (int f = 0; f < 4; ++f)
#pragma unroll
        for (int g = 0; g < 4; ++g)
#pragma unroll
            for (int r = 0; r < 4; ++r) acc[f][g][r] = 0.0f;

    // ---- async copy of one k-chunk into stage s ----
    auto issue_stage = [&](int s, int chunk) {
        const int kB = chunk * TILE_K;
        const uint32_t st = sbase + (uint32_t)s * STAGE_BYTES;
        // A: 128 rows x 8 x 16B  (1024 cp ops / 512 thr = 2 iters)
#pragma unroll
        for (int j = 0; j < 2; ++j) {
            int i = tid + j * THREADS;
            int row = i >> 3, kc = i & 7;
            uint32_t d = st + A_OFF + (uint32_t)(row * 128) + (uint32_t)((kc ^ (row & 7)) << 4);
            cp16(d, g_Ah + (size_t)(mBase + row) * IN_F + kB + kc * 8);
        }
        // B: 256 rows x 8 x 16B  (2048 / 512 = 4 iters)
#pragma unroll
        for (int j = 0; j < 4; ++j) {
            int i = tid + j * THREADS;
            int row = i >> 3, kc = i & 7;
            uint32_t d = st + B_OFF + (uint32_t)(row * 128) + (uint32_t)((kc ^ (row & 7)) << 4);
            cp16(d, g_Wh + (size_t)(nBase + row) * IN_F + kB + kc * 8);
        }
        asm volatile("cp.async.commit_group;" ::: "memory");
    };

    const int rA  = wm * 64 + (lane & 15);
    const int rB  = wn * 32 + (lane & 15);
    const int hi  = lane >> 4;
    const int r7A = rA & 7;
    const int r7B = rB & 7;

    auto compute = [&](int s) {
        const uint32_t st = sbase + (uint32_t)s * STAGE_BYTES;
        const uint32_t sA = st + A_OFF + (uint32_t)(rA * 128);
        const uint32_t sB = st + B_OFF + (uint32_t)(rB * 128);
#pragma unroll
        for (int ks = 0; ks < TILE_K / 16; ++ks) {
            const uint32_t cA = (uint32_t)(((2 * ks + hi) ^ r7A) << 4);
            const uint32_t cB = (uint32_t)(((2 * ks + hi) ^ r7B) << 4);
            uint32_t B0[4], B1[4];
            ldsm4(B0, sB + cB);
            ldsm4(B1, sB + 16 * 128 + cB);
#pragma unroll
            for (int f = 0; f < 4; ++f) {
                uint32_t a[4];
                ldsm4(a, sA + (uint32_t)(f * 16 * 128) + cA);
                mma_f16(acc[f][0], a, B0[0], B0[2]);
                mma_f16(acc[f][1], a, B0[1], B0[3]);
                mma_f16(acc[f][2], a, B1[0], B1[2]);
                mma_f16(acc[f][3], a, B1[1], B1[3]);
            }
        }
    };

    // ---- 3-stage pipeline, ONE sync per iteration ----
    issue_stage(0, 0);
    issue_stage(1, 1);
#pragma unroll 1
    for (int c = 0; c < NC; ++c) {
        if (c + 1 < NC) {
            asm volatile("cp.async.wait_group 1;" ::: "memory");
        } else {
            asm volatile("cp.async.wait_group 0;" ::: "memory");
        }
        __syncthreads();                 // all warps done reading stage (c-1)%3
        if (c + 2 < NC) issue_stage((c + 2) % STAGES, c + 2);
        compute(c % STAGES);
    }

    // ---- epilogue: bias + store ----
    const int row0 = mBase + wm * 64 + (lane >> 2);
    const int col0 = nBase + wn * 32 + (lane & 3) * 2;
#pragma unroll
    for (int g = 0; g < 4; ++g) {
        const float b0 = __ldg(bias + col0 + g * 8);
        const float b1 = __ldg(bias + col0 + g * 8 + 1);
#pragma unroll
        for (int f = 0; f < 4; ++f) {
            const int r = row0 + f * 16;
            float2 v0, v1;
            v0.x = acc[f][g][0] + b0; v0.y = acc[f][g][1] + b1;
            v1.x = acc[f][g][2] + b0; v1.y = acc[f][g][3] + b1;
            *reinterpret_cast<float2*>(out + (size_t)r * OUT_F + col0 + g * 8) = v0;
            *reinterpret_cast<float2*>(out + (size_t)(r + 8) * OUT_F + col0 + g * 8) = v1;
        }
    }
}

// ---------------- launch ----------------
extern "C" void kernel_launch(void* const* d_in, const int* in_sizes, int n_in,
                              void* d_out, int out_size) {
    const float* input    = (const float*)d_in[0];   // [8,2048,4096]
    const float* dense_w  = (const float*)d_in[1];   // [4096,4096]
    const float* dense_b  = (const float*)d_in[2];   // [4096]
    const float* sparse_w = (const float*)d_in[3];   // [NNZ]
    const int*   nz_idx   = (const int*)d_in[4];     // [NNZ] sorted
    float* out = (float*)d_out;                      // [8,2048,4096] fp32
    const int nnz = in_sizes[3];

    prep_convert<<<8192, 256>>>(dense_w, input);
    scatter_fix<<<(nnz + 255) / 256, 256>>>(sparse_w, nz_idx, dense_w, nnz);

    cudaFuncSetAttribute(gemm_kernel, cudaFuncAttributeMaxDynamicSharedMemorySize, SMEM_TOTAL);
    gemm_kernel<<<dim3(OUT_F / TILE_N, M_TOTAL / TILE_M), THREADS, SMEM_TOTAL>>>(dense_b, out);
}

// round 5
// speedup vs baseline: 3.0286x; 1.0164x over previous
#include <cuda_runtime.h>
#include <cuda_fp16.h>
#include <cstdint>

#define IN_F 4096
#define OUT_F 4096
#define M_TOTAL 16384

#define TILE_M 128
#define TILE_N 256
#define SUB_K 64                        // fp16 elems per sub-chunk (128B smem rows)
#define NSUB (IN_F / SUB_K)             // 64 sub-chunks, processed 2 per iteration
#define THREADS 512
#define NBUF 4                          // 4 sub-buffers (2 pairs in flight)

// sub-buffer layout (bytes): A (128 rows x 128B) | B (256 rows x 128B)
#define A_OFF 0
#define B_OFF (TILE_M * 128)                      // 16384
#define BUF_BYTES ((TILE_M + TILE_N) * 128)       // 49152
#define SMEM_TOTAL (NBUF * BUF_BYTES)             // 196608

// ---------------- device scratch ----------------
__device__ __half g_Wh[(size_t)OUT_F * IN_F];
__device__ __half g_Ah[(size_t)M_TOTAL * IN_F];

// ---------------- helpers ----------------
static __device__ __forceinline__ uint32_t smem_u32_of(const void* p) {
    uint32_t r;
    asm("{ .reg .u64 t; cvta.to.shared.u64 t, %1; cvt.u32.u64 %0, t; }" : "=r"(r) : "l"(p));
    return r;
}
static __device__ __forceinline__ void cp16(uint32_t dst, const void* src) {
    asm volatile("cp.async.cg.shared.global [%0], [%1], 16;" :: "r"(dst), "l"(src));
}
static __device__ __forceinline__ void ldsm4(uint32_t (&r)[4], uint32_t a) {
    asm volatile("ldmatrix.sync.aligned.m8n8.x4.shared.b16 {%0,%1,%2,%3}, [%4];"
                 : "=r"(r[0]), "=r"(r[1]), "=r"(r[2]), "=r"(r[3]) : "r"(a));
}
static __device__ __forceinline__ void mma_f16(float (&d)[4], const uint32_t (&a)[4],
                                               uint32_t b0, uint32_t b1) {
    asm volatile(
        "mma.sync.aligned.m16n8k16.row.col.f32.f16.f16.f32 "
        "{%0,%1,%2,%3}, {%4,%5,%6,%7}, {%8,%9}, {%0,%1,%2,%3};"
        : "+f"(d[0]), "+f"(d[1]), "+f"(d[2]), "+f"(d[3])
        : "r"(a[0]), "r"(a[1]), "r"(a[2]), "r"(a[3]), "r"(b0), "r"(b1));
}

// ---------------- prep kernel 1: fp32 -> fp16 convert (W then A) ----------------
__global__ void prep_convert(const float* __restrict__ W, const float* __restrict__ A) {
    const size_t NW4 = (size_t)OUT_F * IN_F / 4;
    const size_t NA4 = (size_t)M_TOTAL * IN_F / 4;
    for (size_t j = (size_t)blockIdx.x * blockDim.x + threadIdx.x; j < NW4 + NA4;
         j += (size_t)gridDim.x * blockDim.x) {
        if (j < NW4) {
            float4 v = reinterpret_cast<const float4*>(W)[j];
            __half2 p0 = __floats2half2_rn(v.x, v.y);
            __half2 p1 = __floats2half2_rn(v.z, v.w);
            reinterpret_cast<uint2*>(g_Wh)[j] =
                make_uint2(*reinterpret_cast<uint32_t*>(&p0), *reinterpret_cast<uint32_t*>(&p1));
        } else {
            size_t i = j - NW4;
            float4 v = reinterpret_cast<const float4*>(A)[i];
            __half2 p0 = __floats2half2_rn(v.x, v.y);
            __half2 p1 = __floats2half2_rn(v.z, v.w);
            reinterpret_cast<uint2*>(g_Ah)[i] =
                make_uint2(*reinterpret_cast<uint32_t*>(&p0), *reinterpret_cast<uint32_t*>(&p1));
        }
    }
}

// ---------------- prep kernel 2: sorted scatter, unique-leader rewrite ----------------
__global__ void scatter_fix(const float* __restrict__ sw, const int* __restrict__ idx,
                            const float* __restrict__ W, int nnz) {
    int i = blockIdx.x * blockDim.x + threadIdx.x;
    if (i >= nnz) return;
    int v = idx[i];
    if (i > 0 && idx[i - 1] == v) return;  // not segment leader
    float s = sw[i];
    for (int j = i + 1; j < nnz && idx[j] == v; ++j) s += sw[j];
    g_Wh[v] = __float2half_rn(W[v] + s);
}

// ---------------- GEMM: out[m,n] = sum_k A[m,k]*W[n,k] + bias[n] ----------------
__global__ void __launch_bounds__(THREADS, 1)
gemm_kernel(const float* __restrict__ bias, float* __restrict__ out, int mOffset) {
    extern __shared__ __align__(128) char smem[];
    const uint32_t sbase = smem_u32_of(smem);

    const int tid  = threadIdx.x;
    const int lane = tid & 31;
    const int wid  = tid >> 5;        // 16 warps
    const int wm   = wid & 1;         // 2 warp rows (64 m each)
    const int wn   = wid >> 1;        // 8 warp cols (32 n each)
    const int mBase = mOffset + blockIdx.y * TILE_M;
    const int nBase = blockIdx.x * TILE_N;

    float acc[4][4][4];
#pragma unroll
    for (int f = 0; f < 4; ++f)
#pragma unroll
        for (int g = 0; g < 4; ++g)
#pragma unroll
            for (int r = 0; r < 4; ++r) acc[f][g][r] = 0.0f;

    // ---- async copy one SUB_K sub-chunk into sub-buffer s (no commit) ----
    auto issue_sub = [&](int s, int sub) {
        const int kB = sub * SUB_K;
        const uint32_t st = sbase + (uint32_t)s * BUF_BYTES;
#pragma unroll
        for (int j = 0; j < 2; ++j) {
            int i = tid + j * THREADS;
            int row = i >> 3, kc = i & 7;
            uint32_t d = st + A_OFF + (uint32_t)(row * 128) + (uint32_t)((kc ^ (row & 7)) << 4);
            cp16(d, g_Ah + (size_t)(mBase + row) * IN_F + kB + kc * 8);
        }
#pragma unroll
        for (int j = 0; j < 4; ++j) {
            int i = tid + j * THREADS;
            int row = i >> 3, kc = i & 7;
            uint32_t d = st + B_OFF + (uint32_t)(row * 128) + (uint32_t)((kc ^ (row & 7)) << 4);
            cp16(d, g_Wh + (size_t)(nBase + row) * IN_F + kB + kc * 8);
        }
    };

    const int rA  = wm * 64 + (lane & 15);
    const int rB  = wn * 32 + (lane & 15);
    const int hi  = lane >> 4;
    const int r7A = rA & 7;
    const int r7B = rB & 7;

    auto compute_sub = [&](int s) {
        const uint32_t st = sbase + (uint32_t)s * BUF_BYTES;
        const uint32_t sA = st + A_OFF + (uint32_t)(rA * 128);
        const uint32_t sB = st + B_OFF + (uint32_t)(rB * 128);
#pragma unroll
        for (int ks = 0; ks < SUB_K / 16; ++ks) {
            const uint32_t cA = (uint32_t)(((2 * ks + hi) ^ r7A) << 4);
            const uint32_t cB = (uint32_t)(((2 * ks + hi) ^ r7B) << 4);
            uint32_t B0[4], B1[4];
            ldsm4(B0, sB + cB);
            ldsm4(B1, sB + 16 * 128 + cB);
#pragma unroll
            for (int f = 0; f < 4; ++f) {
                uint32_t a[4];
                ldsm4(a, sA + (uint32_t)(f * 16 * 128) + cA);
                mma_f16(acc[f][0], a, B0[0], B0[2]);
                mma_f16(acc[f][1], a, B0[1], B0[3]);
                mma_f16(acc[f][2], a, B1[0], B1[2]);
                mma_f16(acc[f][3], a, B1[1], B1[3]);
            }
        }
    };

    // ---- pipeline over sub-chunk PAIRS: 1 barrier + 1 wait per 2 sub-chunks ----
    issue_sub(0, 0);
    issue_sub(1, 1);
    asm volatile("cp.async.commit_group;" ::: "memory");
#pragma unroll 1
    for (int p = 0; p < NSUB / 2; ++p) {
        if (p + 1 < NSUB / 2) {
            issue_sub((2 * p + 2) & 3, 2 * p + 2);
            issue_sub((2 * p + 3) & 3, 2 * p + 3);
            asm volatile("cp.async.commit_group;" ::: "memory");
            asm volatile("cp.async.wait_group 1;" ::: "memory");
        } else {
            asm volatile("cp.async.wait_group 0;" ::: "memory");
        }
        __syncthreads();
        compute_sub((2 * p) & 3);
        compute_sub((2 * p + 1) & 3);
        __syncthreads();
    }

    // ---- epilogue: bias + store ----
    const int row0 = mBase + wm * 64 + (lane >> 2);
    const int col0 = nBase + wn * 32 + (lane & 3) * 2;
#pragma unroll
    for (int g = 0; g < 4; ++g) {
        const float b0 = __ldg(bias + col0 + g * 8);
        const float b1 = __ldg(bias + col0 + g * 8 + 1);
#pragma unroll
        for (int f = 0; f < 4; ++f) {
            const int r = row0 + f * 16;
            float2 v0, v1;
            v0.x = acc[f][g][0] + b0; v0.y = acc[f][g][1] + b1;
            v1.x = acc[f][g][2] + b0; v1.y = acc[f][g][3] + b1;
            *reinterpret_cast<float2*>(out + (size_t)r * OUT_F + col0 + g * 8) = v0;
            *reinterpret_cast<float2*>(out + (size_t)(r + 8) * OUT_F + col0 + g * 8) = v1;
        }
    }
}

// ---------------- launch: [prep, scatter, gemm1, gemm2] -> profiled idx3 = gemm ----
extern "C" void kernel_launch(void* const* d_in, const int* in_sizes, int n_in,
                              void* d_out, int out_size) {
    const float* input    = (const float*)d_in[0];   // [8,2048,4096]
    const float* dense_w  = (const float*)d_in[1];   // [4096,4096]
    const float* dense_b  = (const float*)d_in[2];   // [4096]
    const float* sparse_w = (const float*)d_in[3];   // [NNZ]
    const int*   nz_idx   = (const int*)d_in[4];     // [NNZ] sorted
    float* out = (float*)d_out;                      // [8,2048,4096] fp32
    const int nnz = in_sizes[3];

    prep_convert<<<8192, 256>>>(dense_w, input);
    scatter_fix<<<(nnz + 255) / 256, 256>>>(sparse_w, nz_idx, dense_w, nnz);

    cudaFuncSetAttribute(gemm_kernel, cudaFuncAttributeMaxDynamicSharedMemorySize, SMEM_TOTAL);
    dim3 grid(OUT_F / TILE_N, (M_TOTAL / 2) / TILE_M);   // 16 x 64 = 1024 CTAs each
    gemm_kernel<<<grid, THREADS, SMEM_TOTAL>>>(dense_b, out, 0);
    gemm_kernel<<<grid, THREADS, SMEM_TOTAL>>>(dense_b, out, M_TOTAL / 2);
}